// round 10
// baseline (speedup 1.0000x reference)
#include <cuda_runtime.h>
#include <cuda_bf16.h>
#include <cstdint>

// VectorQuantizer — bf16 mma.sync screening (SINGLE pass, inline candidate capture)
// + lane-parallel exact fp32 rescoring that bit-replicates the reference numerics:
//   dist_k = fl( fl(||z||^2 + ||e_k||^2) - 2*C_k ), C_k = ascending-d fmaf chain from 0
//   argmin first-index tie-break; Zq = fl(z + fl(e-z)); loss = 1.25*mean((e-z)^2)

typedef unsigned int u32;
typedef unsigned long long u64;

#define DDIM 64
#define KC 512
#define HW 4096
#define CHW 262144
#define NVEC 131072
#define THREADS 512
#define WARPS 16
#define GRID 148
#define TILE 256
#define TILEP 260                // padded zfp row stride -> conflict-free afr packing
#define NTILES (NVEC / TILE)     // 512
#define ZQ_ELEMS 8388608
#define LCAP 16                  // per-lane candidate slots

__device__ float g_blocksums[GRID];
__device__ unsigned int g_done = 0;

struct Smem {
    uint4 Bfrag[64 * 2 * 32];    // [nt][half][lane]: half h holds ks=2h,2h+1 frags; 64KB
    float zfp[DDIM * TILEP];     // [d][vector] exact z (padded rows), 66560B
    float Bsh[KC];               // exact ||e_k||^2
    float An[TILE];              // exact ||z||^2
    u64   cbest[TILE];           // packed (S_bits<<32 | k), atomicMin
    float cscore[THREADS * LCAP];// candidate approx scores, 32KB
    u32   cmeta[THREADS * LCAP]; // candidate (row<<16 | k), 32KB
    float red[WARPS];
    float Bmax;
};
#define SMEM_TOTAL ((int)sizeof(Smem))

__device__ __forceinline__ u32 packbf(float lo, float hi) {
    u32 r; asm("cvt.rn.bf16x2.f32 %0, %1, %2;" : "=r"(r) : "f"(hi), "f"(lo)); return r;
}
__device__ __forceinline__ void mma16816(float c[4], const u32 a[4], const u32 b0, const u32 b1) {
    asm volatile(
        "mma.sync.aligned.m16n8k16.row.col.f32.bf16.bf16.f32 "
        "{%0,%1,%2,%3}, {%4,%5,%6,%7}, {%8,%9}, {%0,%1,%2,%3};"
        : "+f"(c[0]), "+f"(c[1]), "+f"(c[2]), "+f"(c[3])
        : "r"(a[0]), "r"(a[1]), "r"(a[2]), "r"(a[3]), "r"(b0), "r"(b1));
}

// 4 approx scores for this warp's m-tile at n-tile nt (2 independent MMA chains).
__device__ __forceinline__ void score4(const Smem* sh, const u32 afr[4][4],
                                       int nt, int lane, int m4, float sc[4]) {
    uint4 q0 = sh->Bfrag[(nt * 2 + 0) * 32 + lane];   // ks0 in (x,y), ks1 in (z,w)
    uint4 q1 = sh->Bfrag[(nt * 2 + 1) * 32 + lane];   // ks2, ks3
    float ca[4] = {0.f,0.f,0.f,0.f}, cb[4] = {0.f,0.f,0.f,0.f};
    mma16816(ca, afr[0], q0.x, q0.y);
    mma16816(cb, afr[2], q1.x, q1.y);
    mma16816(ca, afr[1], q0.z, q0.w);
    mma16816(cb, afr[3], q1.z, q1.w);
    const int k0 = nt * 8 + 2 * m4;
    const float B0 = sh->Bsh[k0], B1 = sh->Bsh[k0 + 1];
    sc[0] = fmaf(-2.f, ca[0] + cb[0], B0);  sc[1] = fmaf(-2.f, ca[1] + cb[1], B1);  // row rA
    sc[2] = fmaf(-2.f, ca[2] + cb[2], B0);  sc[3] = fmaf(-2.f, ca[3] + cb[3], B1);  // row rB
}

// exact rescore (reference numerics) + deterministic lexicographic merge
__device__ __forceinline__ void exact_amin(Smem* sh, const float* __restrict__ E,
                                           int row, int k, float A) {
    const float* er = E + k * DDIM;
    float C = 0.f;
    #pragma unroll 16
    for (int d = 0; d < DDIM; d++) C = fmaf(sh->zfp[d * TILEP + row], __ldg(er + d), C);
    float S = fmaf(-2.f, C, A + sh->Bsh[k]);
    u64 key = ((u64)__float_as_uint(S) << 32) | (u32)k;   // S>0 -> bits order-monotonic
    atomicMin(&sh->cbest[row], key);
}

__global__ void __launch_bounds__(THREADS, 1)
vq_mma_kernel(const float* __restrict__ inp, const float* __restrict__ E,
              float* __restrict__ out, int zq_off)
{
    extern __shared__ char smraw[];
    Smem* sh = (Smem*)smraw;

    const int tid = threadIdx.x;
    const int warp = tid >> 5;
    const int lane = tid & 31;
    const int m4 = lane & 3;
    const int qrow = lane >> 2;

    // ---- one-time staging: B fragments (bf16, uint4 layout) + exact Bsh + Bmax ----
    for (int idx = tid; idx < 64 * 2 * 32; idx += THREADS) {
        int l = idx & 31, half = (idx >> 5) & 1, nt = idx >> 6;
        int kc = nt * 8 + (l >> 2);
        const float* er = E + kc * DDIM;
        int dA = (half * 2) * 16 + 2 * (l & 3);
        int dB = (half * 2 + 1) * 16 + 2 * (l & 3);
        uint4 v;
        v.x = packbf(er[dA],     er[dA + 1]);
        v.y = packbf(er[dA + 8], er[dA + 9]);
        v.z = packbf(er[dB],     er[dB + 1]);
        v.w = packbf(er[dB + 8], er[dB + 9]);
        sh->Bfrag[idx] = v;
    }
    {   // exact ||e||^2 (R2-verbatim), one code per thread (THREADS == KC)
        const int k = tid;
        const float* er = E + k * DDIM;
        float bsum = 0.f;
        #pragma unroll
        for (int d = 0; d < DDIM; d++) { float e = er[d]; bsum = bsum + e * e; }
        sh->Bsh[k] = bsum;
    }
    __syncthreads();
    if (tid == 0) {
        float m = 0.f;
        for (int k = 0; k < KC; k++) m = fmaxf(m, sh->Bsh[k]);
        sh->Bmax = m;
    }
    __syncthreads();
    const float Bmax = sh->Bmax;

    float ls = 0.f;

    for (int tile = blockIdx.x; tile < NTILES; tile += GRID) {
        const int base = tile * TILE;
        const int b = base >> 12, hw0 = base & 4095;
        const float* zsrc = inp + (size_t)b * CHW + hw0;

        __syncthreads();   // protect reused smem across tiles
        for (int i = tid; i < DDIM * TILE / 4; i += THREADS) {   // float4 z staging
            int d = i >> 6, v4 = (i & 63) * 4;
            float4 val = *(const float4*)(zsrc + (size_t)d * HW + v4);
            *(float4*)&sh->zfp[d * TILEP + v4] = val;
        }
        if (tid < TILE) sh->cbest[tid] = 0xFFFFFFFFFFFFFFFFull;
        __syncthreads();
        if (tid < TILE) {
            float A = 0.f;   // exact ||z||^2 ascending d (R2-verbatim)
            #pragma unroll
            for (int d = 0; d < DDIM; d++) { float a = sh->zfp[d * TILEP + tid]; A = A + a * a; }
            sh->An[tid] = A;
        }
        __syncthreads();

        // ---- A fragments: this warp's 16 vectors (one m-tile) ----
        u32 afr[4][4];
        const int rA = warp * 16 + qrow;
        const int rB = rA + 8;
        #pragma unroll
        for (int ks = 0; ks < 4; ks++) {
            const int d0 = ks * 16 + 2 * m4;    // bank = 8*m4 + qrow: conflict-free
            afr[ks][0] = packbf(sh->zfp[d0 * TILEP + rA],       sh->zfp[(d0 + 1) * TILEP + rA]);
            afr[ks][1] = packbf(sh->zfp[d0 * TILEP + rB],       sh->zfp[(d0 + 1) * TILEP + rB]);
            afr[ks][2] = packbf(sh->zfp[(d0 + 8) * TILEP + rA], sh->zfp[(d0 + 9) * TILEP + rA]);
            afr[ks][3] = packbf(sh->zfp[(d0 + 8) * TILEP + rB], sh->zfp[(d0 + 9) * TILEP + rB]);
        }
        const float ArA = sh->An[rA], ArB = sh->An[rB];
        const float margA = 0.025f * sqrtf(ArA * Bmax) + 5e-5f;
        const float margB = 0.025f * sqrtf(ArB * Bmax) + 5e-5f;

        // ---- SINGLE screening pass: running min + inline candidate capture ----
        // running-threshold >= final threshold  ->  stored set is a superset.
        float rm0 = 3.402823466e38f, rm1 = 3.402823466e38f;
        int cnt = 0, ovf = 0;
        const u32 cbase = (u32)tid * LCAP;

        #define PUSH(s, row, kk) do { \
            if (cnt < LCAP) { sh->cscore[cbase + cnt] = (s); \
                              sh->cmeta[cbase + cnt] = ((u32)(row) << 16) | (u32)(kk); } \
            else ovf = 1; \
            cnt++; \
        } while (0)

        #pragma unroll 4
        for (int nt = 0; nt < 64; nt++) {
            float sc[4];
            score4(sh, afr, nt, lane, m4, sc);
            rm0 = fminf(rm0, fminf(sc[0], sc[1]));
            rm1 = fminf(rm1, fminf(sc[2], sc[3]));
            const int k0 = nt * 8 + 2 * m4;
            const float t0 = rm0 + margA, t1 = rm1 + margB;
            if (sc[0] <= t0) PUSH(sc[0], rA, k0);
            if (sc[1] <= t0) PUSH(sc[1], rA, k0 + 1);
            if (sc[2] <= t1) PUSH(sc[2], rB, k0);
            if (sc[3] <= t1) PUSH(sc[3], rB, k0 + 1);
            if ((nt & 15) == 15) {   // fold running min across the 4-lane row group
                rm0 = fminf(rm0, __shfl_xor_sync(0xffffffffu, rm0, 1, 4));
                rm0 = fminf(rm0, __shfl_xor_sync(0xffffffffu, rm0, 2, 4));
                rm1 = fminf(rm1, __shfl_xor_sync(0xffffffffu, rm1, 1, 4));
                rm1 = fminf(rm1, __shfl_xor_sync(0xffffffffu, rm1, 2, 4));
            }
        }
        #undef PUSH

        // final thresholds (rm already folded at nt=63)
        const float thr0 = rm0 + margA;
        const float thr1 = rm1 + margB;

        if (__any_sync(0xffffffffu, ovf)) {
            // fallback (rare): full recompute, exact-rescore hits vs final thr
            for (int nt = 0; nt < 64; nt++) {
                float sc[4];
                score4(sh, afr, nt, lane, m4, sc);
                const int k0 = nt * 8 + 2 * m4;
                if (sc[0] <= thr0) exact_amin(sh, E, rA, k0,     ArA);
                if (sc[1] <= thr0) exact_amin(sh, E, rA, k0 + 1, ArA);
                if (sc[2] <= thr1) exact_amin(sh, E, rB, k0,     ArB);
                if (sc[3] <= thr1) exact_amin(sh, E, rB, k0 + 1, ArB);
            }
        } else {
            // filter stored candidates by final threshold; exact-rescore survivors
            for (int i = 0; i < cnt; i++) {
                float s = sh->cscore[cbase + i];
                u32 meta = sh->cmeta[cbase + i];
                int row = (int)(meta >> 16);
                int k = (int)(meta & 0xffffu);
                const int isA = (row == rA);
                float thr = isA ? thr0 : thr1;
                if (s <= thr) exact_amin(sh, E, row, k, isA ? ArA : ArB);
            }
        }
        __syncthreads();

        // ---- emit: thread handles vector (tid&255), d-range (tid>>8)*32 ----
        {
            const int v = tid & 255;
            const int d0 = (tid >> 8) * 32;
            const int k = (int)(u32)(sh->cbest[v] & 0xffffffffu);
            const float* er = E + k * DDIM + d0;
            float* o = out + zq_off + (size_t)b * CHW + (size_t)d0 * HW + hw0 + v;
            #pragma unroll
            for (int d = 0; d < 32; d++) {
                float zv = sh->zfp[(d0 + d) * TILEP + v];
                float t = er[d] - zv;              // fl(e - z)
                ls += t * t;
                o[(size_t)d * HW] = zv + t;        // fl(z + fl(e-z))
            }
        }
    }

    // ---- deterministic loss reduction + fused finalize ----
    #pragma unroll
    for (int off = 16; off; off >>= 1) ls += __shfl_down_sync(0xffffffffu, ls, off);
    if (lane == 0) sh->red[warp] = ls;
    __syncthreads();
    __shared__ unsigned int s_rank;
    if (tid == 0) {
        float t = 0.f;
        #pragma unroll
        for (int i = 0; i < WARPS; i++) t += sh->red[i];
        g_blocksums[blockIdx.x] = t;
        __threadfence();
        s_rank = atomicAdd(&g_done, 1u);
    }
    __syncthreads();
    if (s_rank == GRID - 1) {
        if (tid < 32) {
            double s = 0.0;
            for (int i = tid; i < GRID; i += 32) s += (double)g_blocksums[i];
            #pragma unroll
            for (int off = 16; off; off >>= 1) s += __shfl_down_sync(0xffffffffu, s, off);
            if (tid == 0) {
                if (zq_off >= 1) out[0] = (float)(s * (1.25 / 8388608.0));
                g_done = 0;   // reset for next graph replay
            }
        }
    }
}

extern "C" void kernel_launch(void* const* d_in, const int* in_sizes, int n_in,
                              void* d_out, int out_size)
{
    const float* inp = (const float*)d_in[0];  // [32,64,64,64] fp32
    const float* E   = (const float*)d_in[1];  // [512,64] fp32
    float* out = (float*)d_out;

    int zq_off = (out_size > ZQ_ELEMS) ? (out_size - ZQ_ELEMS) : 0;

    cudaFuncSetAttribute(vq_mma_kernel, cudaFuncAttributeMaxDynamicSharedMemorySize, SMEM_TOTAL);
    vq_mma_kernel<<<GRID, THREADS, SMEM_TOTAL>>>(inp, E, out, zq_off);
}

// round 11
// speedup vs baseline: 1.0549x; 1.0549x over previous
#include <cuda_runtime.h>
#include <cuda_bf16.h>
#include <cstdint>

// VectorQuantizer — bf16 mma.sync screening (1.25-pass, branchless predicated capture)
// + lane-parallel exact fp32 rescoring that bit-replicates the reference numerics:
//   dist_k = fl( fl(||z||^2 + ||e_k||^2) - 2*C_k ), C_k = ascending-d fmaf chain from 0
//   argmin first-index tie-break; Zq = fl(z + fl(e-z)); loss = 1.25*mean((e-z)^2)

typedef unsigned int u32;
typedef unsigned long long u64;

#define DDIM 64
#define KC 512
#define HW 4096
#define CHW 262144
#define NVEC 131072
#define THREADS 512
#define WARPS 16
#define GRID 148
#define TILE 256
#define TILEP 260                // padded zfp row stride -> conflict-free afr packing
#define NTILES (NVEC / TILE)     // 512
#define ZQ_ELEMS 8388608
#define LCAP 12                  // per-lane capture slots

__device__ float g_blocksums[GRID];
__device__ unsigned int g_done = 0;

struct Smem {
    uint4 Bfrag[64 * 2 * 32];    // [nt][half][lane]: half h holds ks=2h,2h+1; 64KB
    float zfp[DDIM * TILEP];     // [d][vector] exact z (padded rows), 66560B
    float Bsh[KC];               // exact ||e_k||^2
    float An[TILE];              // exact ||z||^2
    u64   cbest[TILE];           // packed (S_bits<<32 | k), atomicMin
    u64   cpack[THREADS * LCAP]; // captures: (score_bits<<32 | row<<9 | k), 48KB
    float red[WARPS];
    float Bmax;
};
#define SMEM_TOTAL ((int)sizeof(Smem))

__device__ __forceinline__ u32 packbf(float lo, float hi) {
    u32 r; asm("cvt.rn.bf16x2.f32 %0, %1, %2;" : "=r"(r) : "f"(hi), "f"(lo)); return r;
}
__device__ __forceinline__ void mma16816(float c[4], const u32 a[4], const u32 b0, const u32 b1) {
    asm volatile(
        "mma.sync.aligned.m16n8k16.row.col.f32.bf16.bf16.f32 "
        "{%0,%1,%2,%3}, {%4,%5,%6,%7}, {%8,%9}, {%0,%1,%2,%3};"
        : "+f"(c[0]), "+f"(c[1]), "+f"(c[2]), "+f"(c[3])
        : "r"(a[0]), "r"(a[1]), "r"(a[2]), "r"(a[3]), "r"(b0), "r"(b1));
}

// 4 approx scores for this warp's m-tile at n-tile nt (2 independent MMA chains).
// Identical every time it is called -> identical score bits.
__device__ __forceinline__ void score4(const Smem* sh, const u32 afr[4][4],
                                       int nt, int lane, int m4, float sc[4]) {
    uint4 q0 = sh->Bfrag[(nt * 2 + 0) * 32 + lane];   // ks0 (x,y), ks1 (z,w)
    uint4 q1 = sh->Bfrag[(nt * 2 + 1) * 32 + lane];   // ks2, ks3
    float ca[4] = {0.f,0.f,0.f,0.f}, cb[4] = {0.f,0.f,0.f,0.f};
    mma16816(ca, afr[0], q0.x, q0.y);
    mma16816(cb, afr[2], q1.x, q1.y);
    mma16816(ca, afr[1], q0.z, q0.w);
    mma16816(cb, afr[3], q1.z, q1.w);
    const int k0 = nt * 8 + 2 * m4;
    const float B0 = sh->Bsh[k0], B1 = sh->Bsh[k0 + 1];
    sc[0] = fmaf(-2.f, ca[0] + cb[0], B0);  sc[1] = fmaf(-2.f, ca[1] + cb[1], B1);  // row rA
    sc[2] = fmaf(-2.f, ca[2] + cb[2], B0);  sc[3] = fmaf(-2.f, ca[3] + cb[3], B1);  // row rB
}

// exact rescore (reference numerics) + deterministic lexicographic merge
__device__ __forceinline__ void exact_amin(Smem* sh, const float* __restrict__ E,
                                           int row, int k, float A) {
    const float* er = E + k * DDIM;
    float C = 0.f;
    #pragma unroll 16
    for (int d = 0; d < DDIM; d++) C = fmaf(sh->zfp[d * TILEP + row], __ldg(er + d), C);
    float S = fmaf(-2.f, C, A + sh->Bsh[k]);
    u64 key = ((u64)__float_as_uint(S) << 32) | (u32)k;   // S>0 -> bits order-monotonic
    atomicMin(&sh->cbest[row], key);
}

__global__ void __launch_bounds__(THREADS, 1)
vq_mma_kernel(const float* __restrict__ inp, const float* __restrict__ E,
              float* __restrict__ out, int zq_off)
{
    extern __shared__ char smraw[];
    Smem* sh = (Smem*)smraw;

    const int tid = threadIdx.x;
    const int warp = tid >> 5;
    const int lane = tid & 31;
    const int m4 = lane & 3;
    const int qrow = lane >> 2;

    // ---- one-time staging: B fragments (bf16, uint4) + exact Bsh + Bmax ----
    for (int idx = tid; idx < 64 * 2 * 32; idx += THREADS) {
        int l = idx & 31, half = (idx >> 5) & 1, nt = idx >> 6;
        int kc = nt * 8 + (l >> 2);
        const float* er = E + kc * DDIM;
        int dA = (half * 2) * 16 + 2 * (l & 3);
        int dB = (half * 2 + 1) * 16 + 2 * (l & 3);
        uint4 v;
        v.x = packbf(er[dA],     er[dA + 1]);
        v.y = packbf(er[dA + 8], er[dA + 9]);
        v.z = packbf(er[dB],     er[dB + 1]);
        v.w = packbf(er[dB + 8], er[dB + 9]);
        sh->Bfrag[idx] = v;
    }
    {   // exact ||e||^2 (R2-verbatim), one code per thread (THREADS == KC)
        const int k = tid;
        const float* er = E + k * DDIM;
        float bsum = 0.f;
        #pragma unroll
        for (int d = 0; d < DDIM; d++) { float e = er[d]; bsum = bsum + e * e; }
        sh->Bsh[k] = bsum;
    }
    __syncthreads();
    if (tid == 0) {
        float m = 0.f;
        for (int k = 0; k < KC; k++) m = fmaxf(m, sh->Bsh[k]);
        sh->Bmax = m;
    }
    __syncthreads();
    const float Bmax = sh->Bmax;

    float ls = 0.f;

    for (int tile = blockIdx.x; tile < NTILES; tile += GRID) {
        const int base = tile * TILE;
        const int b = base >> 12, hw0 = base & 4095;
        const float* zsrc = inp + (size_t)b * CHW + hw0;

        __syncthreads();   // protect reused smem across tiles
        for (int i = tid; i < DDIM * TILE / 4; i += THREADS) {   // float4 z staging
            int d = i >> 6, v4 = (i & 63) * 4;
            float4 val = *(const float4*)(zsrc + (size_t)d * HW + v4);
            *(float4*)&sh->zfp[d * TILEP + v4] = val;
        }
        if (tid < TILE) sh->cbest[tid] = 0xFFFFFFFFFFFFFFFFull;
        __syncthreads();
        if (tid < TILE) {
            float A = 0.f;   // exact ||z||^2 ascending d (R2-verbatim)
            #pragma unroll
            for (int d = 0; d < DDIM; d++) { float a = sh->zfp[d * TILEP + tid]; A = A + a * a; }
            sh->An[tid] = A;
        }
        __syncthreads();

        // ---- A fragments: this warp's 16 vectors (one m-tile) ----
        u32 afr[4][4];
        const int rA = warp * 16 + qrow;
        const int rB = rA + 8;
        #pragma unroll
        for (int ks = 0; ks < 4; ks++) {
            const int d0 = ks * 16 + 2 * m4;    // bank = 8*m4 + qrow: conflict-free
            afr[ks][0] = packbf(sh->zfp[d0 * TILEP + rA],       sh->zfp[(d0 + 1) * TILEP + rA]);
            afr[ks][1] = packbf(sh->zfp[d0 * TILEP + rB],       sh->zfp[(d0 + 1) * TILEP + rB]);
            afr[ks][2] = packbf(sh->zfp[(d0 + 8) * TILEP + rA], sh->zfp[(d0 + 9) * TILEP + rA]);
            afr[ks][3] = packbf(sh->zfp[(d0 + 8) * TILEP + rB], sh->zfp[(d0 + 9) * TILEP + rB]);
        }
        const float ArA = sh->An[rA], ArB = sh->An[rB];
        const float margA = 0.025f * sqrtf(ArA * Bmax) + 5e-5f;
        const float margB = 0.025f * sqrtf(ArB * Bmax) + 5e-5f;

        // ---- phase A: 1/4-pass pure branchless min (codes 0..127 per row) ----
        float rm0 = 3.402823466e38f, rm1 = 3.402823466e38f;
        #pragma unroll 4
        for (int nt = 0; nt < 16; nt++) {
            float sc[4];
            score4(sh, afr, nt, lane, m4, sc);
            rm0 = fminf(rm0, fminf(sc[0], sc[1]));
            rm1 = fminf(rm1, fminf(sc[2], sc[3]));
        }
        rm0 = fminf(rm0, __shfl_xor_sync(0xffffffffu, rm0, 1, 4));
        rm0 = fminf(rm0, __shfl_xor_sync(0xffffffffu, rm0, 2, 4));
        rm1 = fminf(rm1, __shfl_xor_sync(0xffffffffu, rm1, 1, 4));
        rm1 = fminf(rm1, __shfl_xor_sync(0xffffffffu, rm1, 2, 4));

        // ---- phase B: full pass, branchless predicated capture ----
        // running thr >= final thr -> stored set is a superset of final in-margin set.
        int cnt = 0;
        const u32 cbase = (u32)tid * LCAP;
        #pragma unroll 4
        for (int nt = 0; nt < 64; nt++) {
            float sc[4];
            score4(sh, afr, nt, lane, m4, sc);
            const int k0 = nt * 8 + 2 * m4;
            const float t0 = rm0 + margA, t1 = rm1 + margB;
            #pragma unroll
            for (int c = 0; c < 4; c++) {
                const float s = sc[c];
                const int row = (c < 2) ? rA : rB;
                const int kk = k0 + (c & 1);
                const bool p = s <= ((c < 2) ? t0 : t1);
                u64 pk = ((u64)__float_as_uint(s) << 32) | ((u32)row << 9) | (u32)kk;
                u64* addr = &sh->cpack[cbase + (u32)min(cnt, LCAP - 1)];
                if (p) *addr = pk;        // single predicated STS.64 (no branch)
                cnt += (int)p;
            }
            rm0 = fminf(rm0, fminf(sc[0], sc[1]));
            rm1 = fminf(rm1, fminf(sc[2], sc[3]));
            if ((nt & 15) == 15) {   // tighten across the 4-lane row group
                rm0 = fminf(rm0, __shfl_xor_sync(0xffffffffu, rm0, 1, 4));
                rm0 = fminf(rm0, __shfl_xor_sync(0xffffffffu, rm0, 2, 4));
                rm1 = fminf(rm1, __shfl_xor_sync(0xffffffffu, rm1, 1, 4));
                rm1 = fminf(rm1, __shfl_xor_sync(0xffffffffu, rm1, 2, 4));
            }
        }

        const float thr0 = rm0 + margA;   // rm folded at nt=63 -> final thresholds
        const float thr1 = rm1 + margB;

        if (__any_sync(0xffffffffu, cnt > LCAP)) {
            // fallback (rare): recompute scan, exact-rescore all final-thr hits
            for (int nt = 0; nt < 64; nt++) {
                float sc[4];
                score4(sh, afr, nt, lane, m4, sc);
                const int k0 = nt * 8 + 2 * m4;
                if (sc[0] <= thr0) exact_amin(sh, E, rA, k0,     ArA);
                if (sc[1] <= thr0) exact_amin(sh, E, rA, k0 + 1, ArA);
                if (sc[2] <= thr1) exact_amin(sh, E, rB, k0,     ArB);
                if (sc[3] <= thr1) exact_amin(sh, E, rB, k0 + 1, ArB);
            }
        } else {
            // lane-parallel: filter captures by final thr, exact-rescore survivors
            int maxb = cnt;
            #pragma unroll
            for (int off = 16; off; off >>= 1)
                maxb = max(maxb, __shfl_xor_sync(0xffffffffu, maxb, off));
            for (int i = 0; i < maxb; i++) {
                if (i < cnt) {
                    u64 pk = sh->cpack[cbase + i];
                    float s = __uint_as_float((u32)(pk >> 32));
                    int row = (int)((pk >> 9) & 0xFF);
                    int k = (int)(pk & 0x1FF);
                    const bool isA = (row == rA);
                    if (s <= (isA ? thr0 : thr1))
                        exact_amin(sh, E, row, k, isA ? ArA : ArB);
                }
            }
        }
        __syncthreads();

        // ---- emit: thread handles vector (tid&255), d-range (tid>>8)*32 ----
        {
            const int v = tid & 255;
            const int d0 = (tid >> 8) * 32;
            const int k = (int)(u32)(sh->cbest[v] & 0xffffffffu);
            const float* er = E + k * DDIM + d0;
            float* o = out + zq_off + (size_t)b * CHW + (size_t)d0 * HW + hw0 + v;
            #pragma unroll
            for (int d = 0; d < 32; d++) {
                float zv = sh->zfp[(d0 + d) * TILEP + v];
                float t = er[d] - zv;              // fl(e - z)
                ls += t * t;
                o[(size_t)d * HW] = zv + t;        // fl(z + fl(e-z))
            }
        }
    }

    // ---- deterministic loss reduction + fused finalize ----
    #pragma unroll
    for (int off = 16; off; off >>= 1) ls += __shfl_down_sync(0xffffffffu, ls, off);
    if (lane == 0) sh->red[warp] = ls;
    __syncthreads();
    __shared__ unsigned int s_rank;
    if (tid == 0) {
        float t = 0.f;
        #pragma unroll
        for (int i = 0; i < WARPS; i++) t += sh->red[i];
        g_blocksums[blockIdx.x] = t;
        __threadfence();
        s_rank = atomicAdd(&g_done, 1u);
    }
    __syncthreads();
    if (s_rank == GRID - 1) {
        if (tid < 32) {
            double s = 0.0;
            for (int i = tid; i < GRID; i += 32) s += (double)g_blocksums[i];
            #pragma unroll
            for (int off = 16; off; off >>= 1) s += __shfl_down_sync(0xffffffffu, s, off);
            if (tid == 0) {
                if (zq_off >= 1) out[0] = (float)(s * (1.25 / 8388608.0));
                g_done = 0;   // reset for next graph replay
            }
        }
    }
}

extern "C" void kernel_launch(void* const* d_in, const int* in_sizes, int n_in,
                              void* d_out, int out_size)
{
    const float* inp = (const float*)d_in[0];  // [32,64,64,64] fp32
    const float* E   = (const float*)d_in[1];  // [512,64] fp32
    float* out = (float*)d_out;

    int zq_off = (out_size > ZQ_ELEMS) ? (out_size - ZQ_ELEMS) : 0;

    cudaFuncSetAttribute(vq_mma_kernel, cudaFuncAttributeMaxDynamicSharedMemorySize, SMEM_TOTAL);
    vq_mma_kernel<<<GRID, THREADS, SMEM_TOTAL>>>(inp, E, out, zq_off);
}

// round 12
// speedup vs baseline: 2.3556x; 2.2330x over previous
#include <cuda_runtime.h>
#include <cuda_bf16.h>
#include <cstdint>

// VectorQuantizer — bf16 mma.sync screening (two-pass, R9 structure) + lane-parallel
// exact fp32 rescoring that bit-replicates the reference numerics:
//   dist_k = fl( fl(||z||^2 + ||e_k||^2) - 2*C_k ), C_k = ascending-d fmaf chain from 0
//   argmin first-index tie-break; Zq = fl(z + fl(e-z)); loss = 1.25*mean((e-z)^2)

typedef unsigned int u32;
typedef unsigned long long u64;

#define DDIM 64
#define KC 512
#define HW 4096
#define CHW 262144
#define NVEC 131072
#define THREADS 512
#define WARPS 16
#define GRID 148
#define TILE 256
#define TILEP 260                // padded zfp row stride -> conflict-free afr packing
#define NTILES (NVEC / TILE)     // 512
#define ZQ_ELEMS 8388608
#define LCAP 8                   // per-lane candidate slots

__device__ float g_blocksums[GRID];
__device__ unsigned int g_done = 0;

struct Smem {
    uint4 Bfrag[64 * 2 * 32];    // [nt][half][lane]: half h holds ks=2h,2h+1; 64KB
    float zfp[DDIM * TILEP];     // [d][vector] exact z (padded rows), 66560B
    float Bsh[KC];               // exact ||e_k||^2
    float An[TILE];              // exact ||z||^2
    u64   cbest[TILE];           // packed (S_bits<<32 | k), atomicMin
    u32   cand[THREADS * LCAP];  // per-lane candidate lists, 16KB
    float red[WARPS];
    float Bmax;
};
#define SMEM_TOTAL ((int)sizeof(Smem))

__device__ __forceinline__ u32 packbf(float lo, float hi) {
    u32 r; asm("cvt.rn.bf16x2.f32 %0, %1, %2;" : "=r"(r) : "f"(hi), "f"(lo)); return r;
}
__device__ __forceinline__ void mma16816(float c[4], const u32 a[4], const u32 b0, const u32 b1) {
    asm volatile(
        "mma.sync.aligned.m16n8k16.row.col.f32.bf16.bf16.f32 "
        "{%0,%1,%2,%3}, {%4,%5,%6,%7}, {%8,%9}, {%0,%1,%2,%3};"
        : "+f"(c[0]), "+f"(c[1]), "+f"(c[2]), "+f"(c[3])
        : "r"(a[0]), "r"(a[1]), "r"(a[2]), "r"(a[3]), "r"(b0), "r"(b1));
}

// 4 approx scores for this warp's m-tile at n-tile nt (2 independent MMA chains).
// Identical in pass 1 and pass 2 -> identical score bits.
__device__ __forceinline__ void score4(const Smem* sh, const u32 afr[4][4],
                                       int nt, int lane, int m4, float sc[4]) {
    uint4 q0 = sh->Bfrag[(nt * 2 + 0) * 32 + lane];   // ks0 (x,y), ks1 (z,w)
    uint4 q1 = sh->Bfrag[(nt * 2 + 1) * 32 + lane];   // ks2, ks3
    float ca[4] = {0.f,0.f,0.f,0.f}, cb[4] = {0.f,0.f,0.f,0.f};
    mma16816(ca, afr[0], q0.x, q0.y);
    mma16816(cb, afr[2], q1.x, q1.y);
    mma16816(ca, afr[1], q0.z, q0.w);
    mma16816(cb, afr[3], q1.z, q1.w);
    const int k0 = nt * 8 + 2 * m4;
    const float B0 = sh->Bsh[k0], B1 = sh->Bsh[k0 + 1];
    sc[0] = fmaf(-2.f, ca[0] + cb[0], B0);  sc[1] = fmaf(-2.f, ca[1] + cb[1], B1);  // row rA
    sc[2] = fmaf(-2.f, ca[2] + cb[2], B0);  sc[3] = fmaf(-2.f, ca[3] + cb[3], B1);  // row rB
}

// exact rescore (reference numerics; float4 loads, fmaf chain order unchanged)
// + deterministic lexicographic merge
__device__ __forceinline__ void exact_amin(Smem* sh, const float* __restrict__ E,
                                           int row, int k, float A) {
    const float4* er4 = (const float4*)(E + k * DDIM);
    float C = 0.f;
    #pragma unroll
    for (int i = 0; i < DDIM / 4; i++) {
        float4 e = __ldg(er4 + i);
        C = fmaf(sh->zfp[(4 * i + 0) * TILEP + row], e.x, C);
        C = fmaf(sh->zfp[(4 * i + 1) * TILEP + row], e.y, C);
        C = fmaf(sh->zfp[(4 * i + 2) * TILEP + row], e.z, C);
        C = fmaf(sh->zfp[(4 * i + 3) * TILEP + row], e.w, C);
    }
    float S = fmaf(-2.f, C, A + sh->Bsh[k]);
    u64 key = ((u64)__float_as_uint(S) << 32) | (u32)k;   // S>0 -> bits order-monotonic
    atomicMin(&sh->cbest[row], key);
}

__global__ void __launch_bounds__(THREADS, 1)
vq_mma_kernel(const float* __restrict__ inp, const float* __restrict__ E,
              float* __restrict__ out, int zq_off)
{
    extern __shared__ char smraw[];
    Smem* sh = (Smem*)smraw;

    const int tid = threadIdx.x;
    const int warp = tid >> 5;
    const int lane = tid & 31;
    const int m4 = lane & 3;
    const int qrow = lane >> 2;

    // ---- one-time staging: B fragments (bf16, uint4) + exact Bsh + Bmax ----
    for (int idx = tid; idx < 64 * 2 * 32; idx += THREADS) {
        int l = idx & 31, half = (idx >> 5) & 1, nt = idx >> 6;
        int kc = nt * 8 + (l >> 2);
        const float* er = E + kc * DDIM;
        int dA = (half * 2) * 16 + 2 * (l & 3);
        int dB = (half * 2 + 1) * 16 + 2 * (l & 3);
        uint4 v;
        v.x = packbf(er[dA],     er[dA + 1]);
        v.y = packbf(er[dA + 8], er[dA + 9]);
        v.z = packbf(er[dB],     er[dB + 1]);
        v.w = packbf(er[dB + 8], er[dB + 9]);
        sh->Bfrag[idx] = v;
    }
    {   // exact ||e||^2 (R2-verbatim), one code per thread (THREADS == KC)
        const int k = tid;
        const float* er = E + k * DDIM;
        float bsum = 0.f;
        #pragma unroll
        for (int d = 0; d < DDIM; d++) { float e = er[d]; bsum = bsum + e * e; }
        sh->Bsh[k] = bsum;
    }
    __syncthreads();
    if (tid == 0) {
        float m = 0.f;
        for (int k = 0; k < KC; k++) m = fmaxf(m, sh->Bsh[k]);
        sh->Bmax = m;
    }
    __syncthreads();
    const float Bmax = sh->Bmax;

    float ls = 0.f;

    for (int tile = blockIdx.x; tile < NTILES; tile += GRID) {
        const int base = tile * TILE;
        const int b = base >> 12, hw0 = base & 4095;
        const float* zsrc = inp + (size_t)b * CHW + hw0;

        __syncthreads();   // protect reused smem across tiles
        for (int i = tid; i < DDIM * TILE / 4; i += THREADS) {   // float4 z staging
            int d = i >> 6, v4 = (i & 63) * 4;
            float4 val = *(const float4*)(zsrc + (size_t)d * HW + v4);
            *(float4*)&sh->zfp[d * TILEP + v4] = val;
        }
        if (tid < TILE) sh->cbest[tid] = 0xFFFFFFFFFFFFFFFFull;
        __syncthreads();
        if (tid < TILE) {
            float A = 0.f;   // exact ||z||^2 ascending d (R2-verbatim)
            #pragma unroll
            for (int d = 0; d < DDIM; d++) { float a = sh->zfp[d * TILEP + tid]; A = A + a * a; }
            sh->An[tid] = A;
        }
        __syncthreads();

        // ---- A fragments: this warp's 16 vectors (one m-tile) ----
        u32 afr[4][4];
        const int rA = warp * 16 + qrow;
        const int rB = rA + 8;
        #pragma unroll
        for (int ks = 0; ks < 4; ks++) {
            const int d0 = ks * 16 + 2 * m4;    // bank = 8*m4 + qrow: conflict-free
            afr[ks][0] = packbf(sh->zfp[d0 * TILEP + rA],       sh->zfp[(d0 + 1) * TILEP + rA]);
            afr[ks][1] = packbf(sh->zfp[d0 * TILEP + rB],       sh->zfp[(d0 + 1) * TILEP + rB]);
            afr[ks][2] = packbf(sh->zfp[(d0 + 8) * TILEP + rA], sh->zfp[(d0 + 9) * TILEP + rA]);
            afr[ks][3] = packbf(sh->zfp[(d0 + 8) * TILEP + rB], sh->zfp[(d0 + 9) * TILEP + rB]);
        }
        const float ArA = sh->An[rA], ArB = sh->An[rB];

        // ---- pass 1: branchless running min ----
        float rm0 = 3.402823466e38f, rm1 = 3.402823466e38f;
        #pragma unroll 4
        for (int nt = 0; nt < 64; nt++) {
            float sc[4];
            score4(sh, afr, nt, lane, m4, sc);
            rm0 = fminf(rm0, fminf(sc[0], sc[1]));
            rm1 = fminf(rm1, fminf(sc[2], sc[3]));
        }
        float gm0 = rm0, gm1 = rm1;
        gm0 = fminf(gm0, __shfl_xor_sync(0xffffffffu, gm0, 1, 4));
        gm0 = fminf(gm0, __shfl_xor_sync(0xffffffffu, gm0, 2, 4));
        gm1 = fminf(gm1, __shfl_xor_sync(0xffffffffu, gm1, 1, 4));
        gm1 = fminf(gm1, __shfl_xor_sync(0xffffffffu, gm1, 2, 4));
        const float thr0 = gm0 + (0.025f * sqrtf(ArA * Bmax) + 5e-5f);
        const float thr1 = gm1 + (0.025f * sqrtf(ArB * Bmax) + 5e-5f);

        // ---- pass 2: recompute, collect hits into per-lane smem lists ----
        int myCnt = 0;
        const u32 cbase = tid * LCAP;
        #pragma unroll 4
        for (int nt = 0; nt < 64; nt++) {
            float sc[4];
            score4(sh, afr, nt, lane, m4, sc);
            const int k0 = nt * 8 + 2 * m4;
            if (sc[0] <= thr0) { if (myCnt < LCAP) sh->cand[cbase + myCnt] = ((u32)rA << 16) | (u32)k0;       myCnt++; }
            if (sc[1] <= thr0) { if (myCnt < LCAP) sh->cand[cbase + myCnt] = ((u32)rA << 16) | (u32)(k0 + 1); myCnt++; }
            if (sc[2] <= thr1) { if (myCnt < LCAP) sh->cand[cbase + myCnt] = ((u32)rB << 16) | (u32)k0;       myCnt++; }
            if (sc[3] <= thr1) { if (myCnt < LCAP) sh->cand[cbase + myCnt] = ((u32)rB << 16) | (u32)(k0 + 1); myCnt++; }
        }

        const int ovf = (myCnt > LCAP);
        if (__any_sync(0xffffffffu, ovf)) {
            // fallback (P ~ 0): inline exact over every hit; min-merge is idempotent
            for (int nt = 0; nt < 64; nt++) {
                float sc[4];
                score4(sh, afr, nt, lane, m4, sc);
                const int k0 = nt * 8 + 2 * m4;
                if (sc[0] <= thr0) exact_amin(sh, E, rA, k0,     ArA);
                if (sc[1] <= thr0) exact_amin(sh, E, rA, k0 + 1, ArA);
                if (sc[2] <= thr1) exact_amin(sh, E, rB, k0,     ArB);
                if (sc[3] <= thr1) exact_amin(sh, E, rB, k0 + 1, ArB);
            }
        } else {
            // lane-parallel exact rescoring: each lane walks its own list
            int maxb = myCnt;
            #pragma unroll
            for (int off = 16; off; off >>= 1)
                maxb = max(maxb, __shfl_xor_sync(0xffffffffu, maxb, off));
            for (int i = 0; i < maxb; i++) {
                if (i < myCnt) {
                    u32 ent = sh->cand[cbase + i];
                    int row = ent >> 16, k = ent & 0xffff;
                    exact_amin(sh, E, row, k, sh->An[row]);
                }
            }
        }
        __syncthreads();

        // ---- emit: thread handles vector (tid&255), d-range (tid>>8)*32 ----
        {
            const int v = tid & 255;
            const int d0 = (tid >> 8) * 32;
            const int k = (int)(u32)(sh->cbest[v] & 0xffffffffu);
            const float4* er4 = (const float4*)(E + k * DDIM + d0);
            float* o = out + zq_off + (size_t)b * CHW + (size_t)d0 * HW + hw0 + v;
            #pragma unroll
            for (int i = 0; i < 8; i++) {
                float4 e = __ldg(er4 + i);
                float zv, t;
                zv = sh->zfp[(d0 + 4 * i + 0) * TILEP + v];
                t = e.x - zv; ls += t * t; o[(size_t)(4 * i + 0) * HW] = zv + t;
                zv = sh->zfp[(d0 + 4 * i + 1) * TILEP + v];
                t = e.y - zv; ls += t * t; o[(size_t)(4 * i + 1) * HW] = zv + t;
                zv = sh->zfp[(d0 + 4 * i + 2) * TILEP + v];
                t = e.z - zv; ls += t * t; o[(size_t)(4 * i + 2) * HW] = zv + t;
                zv = sh->zfp[(d0 + 4 * i + 3) * TILEP + v];
                t = e.w - zv; ls += t * t; o[(size_t)(4 * i + 3) * HW] = zv + t;
            }
        }
    }

    // ---- deterministic loss reduction + fused finalize ----
    #pragma unroll
    for (int off = 16; off; off >>= 1) ls += __shfl_down_sync(0xffffffffu, ls, off);
    if (lane == 0) sh->red[warp] = ls;
    __syncthreads();
    __shared__ unsigned int s_rank;
    if (tid == 0) {
        float t = 0.f;
        #pragma unroll
        for (int i = 0; i < WARPS; i++) t += sh->red[i];
        g_blocksums[blockIdx.x] = t;
        __threadfence();
        s_rank = atomicAdd(&g_done, 1u);
    }
    __syncthreads();
    if (s_rank == GRID - 1) {
        if (tid < 32) {
            double s = 0.0;
            for (int i = tid; i < GRID; i += 32) s += (double)g_blocksums[i];
            #pragma unroll
            for (int off = 16; off; off >>= 1) s += __shfl_down_sync(0xffffffffu, s, off);
            if (tid == 0) {
                if (zq_off >= 1) out[0] = (float)(s * (1.25 / 8388608.0));
                g_done = 0;   // reset for next graph replay
            }
        }
    }
}

extern "C" void kernel_launch(void* const* d_in, const int* in_sizes, int n_in,
                              void* d_out, int out_size)
{
    const float* inp = (const float*)d_in[0];  // [32,64,64,64] fp32
    const float* E   = (const float*)d_in[1];  // [512,64] fp32
    float* out = (float*)d_out;

    int zq_off = (out_size > ZQ_ELEMS) ? (out_size - ZQ_ELEMS) : 0;

    cudaFuncSetAttribute(vq_mma_kernel, cudaFuncAttributeMaxDynamicSharedMemorySize, SMEM_TOTAL);
    vq_mma_kernel<<<GRID, THREADS, SMEM_TOTAL>>>(inp, E, out, zq_off);
}